// round 4
// baseline (speedup 1.0000x reference)
#include <cuda_runtime.h>

// Fixed shape: depthin (1,1,480,640) float32 -> scalar float32.
#define ROWS 480
#define COLS 640
#define TH   16
#define TW   32
#define NT   (TH * TW)    // 512
#define S    7
#define P    3
#define SMH  (TH + 2*P)   // 22
#define SMW  (TW + 2*P)   // 38
#define NBX  (COLS / TW)  // 20
#define NBY  (ROWS / TH)  // 30
#define NB   (NBX * NBY)  // 600

__device__ float g_blocksums[NB];
__device__ unsigned int g_count = 0;   // reset to 0 by the last block each run

typedef unsigned long long u64;

__device__ __forceinline__ float fsqrt_approx(float x) {
    float r;
    asm("sqrt.approx.f32 %0, %1;" : "=f"(r) : "f"(x));
    return r;
}
__device__ __forceinline__ u64 pack2(float lo, float hi) {
    u64 r; asm("mov.b64 %0, {%1, %2};" : "=l"(r) : "f"(lo), "f"(hi)); return r;
}
__device__ __forceinline__ void unpack2(u64 v, float& lo, float& hi) {
    asm("mov.b64 {%0, %1}, %2;" : "=f"(lo), "=f"(hi) : "l"(v));
}
__device__ __forceinline__ u64 fma2(u64 a, u64 b, u64 c) {
    u64 d; asm("fma.rn.f32x2 %0, %1, %2, %3;" : "=l"(d) : "l"(a), "l"(b), "l"(c)); return d;
}
__device__ __forceinline__ u64 mul2(u64 a, u64 b) {
    u64 d; asm("mul.rn.f32x2 %0, %1, %2;" : "=l"(d) : "l"(a), "l"(b)); return d;
}
__device__ __forceinline__ u64 add2(u64 a, u64 b) {
    u64 d; asm("add.rn.f32x2 %0, %1, %2;" : "=l"(d) : "l"(a), "l"(b)); return d;
}

__global__ __launch_bounds__(NT)
void stdev_fused_kernel(const float* __restrict__ depth, float* __restrict__ out) {
    __shared__ float sz[SMH][SMW];
    __shared__ float wsum[NT / 32];   // 16 warps
    __shared__ int   is_last;

    const float inv_fx = (float)(1.0 / 582.6244816773795);
    const float inv_fy = (float)(1.0 / 582.6910327098864);
    const float cx = 313.0447587080473f;
    const float cy = 238.44389626620386f;

    const int bj0 = blockIdx.x * TW;
    const int bi0 = blockIdx.y * TH;
    const int tid = threadIdx.y * TW + threadIdx.x;
    const int bid = blockIdx.y * NBX + blockIdx.x;

    // Cooperative z-tile load with +/-3 halo (clamped; clamped halo cells are
    // never addressed by any clamped window of an interior pixel).
    #pragma unroll
    for (int idx = tid; idx < SMH * SMW; idx += NT) {
        int lr = idx / SMW, lc = idx % SMW;
        int gr = min(max(bi0 + lr - P, 0), ROWS - 1);
        int gc = min(max(bj0 + lc - P, 0), COLS - 1);
        float d = depth[gr * COLS + gc];
        sz[lr][lc] = (d > 0.0f && d < 1.01f) ? d * 1e-3f : 0.0f;
    }
    __syncthreads();

    const int i = bi0 + threadIdx.y;
    const int j = bj0 + threadIdx.x;

    // Clamped window start (reproduces reference idif/jdif boundary shift).
    const int istart = min(max(i - P, 0), ROWS - S);
    const int jstart = min(max(j - P, 0), COLS - S);
    const int smr0 = istart - bi0 + P;
    const int smc0 = jstart - bj0 + P;

    const float z0 = sz[threadIdx.y + P][threadIdx.x + P];
    const float x0 = z0 * (((float)j - cx) * inv_fx);
    const float y0 = z0 * (((float)i - cy) * inv_fy);

    // Negated per-column / per-row scales so dx = fma(zn, -cs, x0) etc.
    float negcs[S], negrs[S];
    #pragma unroll
    for (int t = 0; t < S; t++) negcs[t] = -(((float)(jstart + t) - cx) * inv_fx);
    #pragma unroll
    for (int s = 0; s < S; s++) negrs[s] = -(((float)(istart + s) - cy) * inv_fy);

    u64 negcs2[3];
    negcs2[0] = pack2(negcs[0], negcs[1]);
    negcs2[1] = pack2(negcs[2], negcs[3]);
    negcs2[2] = pack2(negcs[4], negcs[5]);

    const u64 x02 = pack2(x0, x0);
    const u64 y02 = pack2(y0, y0);
    const u64 z02 = pack2(z0, z0);
    const u64 cm1 = pack2(-1.0f, -1.0f);

    u64 sumd2  = pack2(0.0f, 0.0f);
    u64 sumsq2 = pack2(0.0f, 0.0f);
    float sumd1 = 0.0f, sumsq1 = 0.0f;

    #pragma unroll
    for (int s = 0; s < S; s++) {
        const float* row = &sz[smr0 + s][smc0];
        const u64 negrs2 = pack2(negrs[s], negrs[s]);

        // 3 column-pairs, packed f32x2
        #pragma unroll
        for (int p = 0; p < 3; p++) {
            u64 zn2 = pack2(row[2 * p], row[2 * p + 1]);
            u64 dz2 = fma2(zn2, cm1, z02);          // z0 - zn
            u64 dx2 = fma2(zn2, negcs2[p], x02);    // x0 - zn*cs
            u64 dy2 = fma2(zn2, negrs2, y02);       // y0 - zn*rs
            u64 m   = mul2(dz2, dz2);
            m       = fma2(dy2, dy2, m);
            u64 sq2 = fma2(dx2, dx2, m);
            sumsq2  = add2(sumsq2, sq2);
            float q0, q1; unpack2(sq2, q0, q1);
            u64 d2 = pack2(fsqrt_approx(q0), fsqrt_approx(q1));
            sumd2  = add2(sumd2, d2);
        }
        // remainder column t=6 (scalar)
        {
            float zn = row[6];
            float dz = z0 - zn;
            float dx = fmaf(zn, negcs[6], x0);
            float dy = fmaf(zn, negrs[s], y0);
            float sq = fmaf(dx, dx, fmaf(dy, dy, dz * dz));
            sumsq1 += sq;
            sumd1  += fsqrt_approx(sq);
        }
    }

    float sdl, sdh, ssl, ssh;
    unpack2(sumd2, sdl, sdh);
    unpack2(sumsq2, ssl, ssh);
    const float sumd  = sdl + sdh + sumd1;
    const float sumsq = ssl + ssh + sumsq1;

    // Unbiased variance over the 49 distances.
    float var = (sumsq - sumd * sumd * (1.0f / 49.0f)) * (1.0f / 48.0f);
    float dev = (z0 > 0.0f) ? sqrtf(fmaxf(var, 0.0f)) : 0.0f;

    // Block reduction (deterministic shuffle tree).
    float v = dev;
    #pragma unroll
    for (int o = 16; o; o >>= 1) v += __shfl_xor_sync(0xffffffffu, v, o);
    if ((tid & 31) == 0) wsum[tid >> 5] = v;
    __syncthreads();

    if (tid < 16) {
        float w = wsum[tid];
        #pragma unroll
        for (int o = 8; o; o >>= 1) w += __shfl_xor_sync(0x0000ffffu, w, o, 16);
        if (tid == 0) {
            g_blocksums[bid] = w;
            __threadfence();
            unsigned int cnt = atomicAdd(&g_count, 1u);
            is_last = (cnt == NB - 1);
        }
    }
    __syncthreads();

    // Last finished block performs the final reduction (fixed order -> deterministic).
    if (is_last) {
        __threadfence();
        float srun = 0.0f;
        for (int idx = tid; idx < NB; idx += NT)
            srun += ((volatile float*)g_blocksums)[idx];
        #pragma unroll
        for (int o = 16; o; o >>= 1) srun += __shfl_xor_sync(0xffffffffu, srun, o);
        if ((tid & 31) == 0) wsum[tid >> 5] = srun;
        __syncthreads();
        if (tid < 16) {
            float w = wsum[tid];
            #pragma unroll
            for (int o = 8; o; o >>= 1) w += __shfl_xor_sync(0x0000ffffu, w, o, 16);
            if (tid == 0) {
                out[0] = w * 100.0f;
                g_count = 0;   // re-arm for next graph replay
            }
        }
    }
}

extern "C" void kernel_launch(void* const* d_in, const int* in_sizes, int n_in,
                              void* d_out, int out_size) {
    const float* depth = (const float*)d_in[0];   // depthin (1,1,480,640)
    float* out = (float*)d_out;
    dim3 grid(NBX, NBY);
    dim3 block(TW, TH);
    stdev_fused_kernel<<<grid, block>>>(depth, out);
}